// round 11
// baseline (speedup 1.0000x reference)
#include <cuda_runtime.h>
#include <cuda_fp16.h>
#include <cstdint>
#include <math.h>

constexpr int N = 8192;
constexpr int D = 128;
// features pre-scaled by sqrt(10*log2(e)); Gram accumulators are exp2 args
constexpr float PRE_SCALE = 3.79828256f;

constexpr int NT     = 64;
constexpr int NTILES = 2080;
constexpr int GRID   = 296;                      // 2 CTAs x 148 SMs, all resident

constexpr int ROWB  = 272;
constexpr int ATILE = 128 * ROWB;
constexpr int SMEM_A   = 0;
constexpr int SMEM_B0  = ATILE;
constexpr int SMEM_B1  = 2 * ATILE;
constexpr int SMEM_RED = 3 * ATILE;
constexpr int SMEM_BYTES = 3 * ATILE + 2048;     // 106496 B; 2 CTAs = 208 KB

__device__ uint4 g_hv[N * D / 8];
__device__ float g_total[N];
__device__ float g_pos[N];
__device__ float g_loss;
__device__ unsigned g_bar;                       // monotonic barrier counter
#define G_H ((__half*)g_hv)

__device__ __forceinline__ uint32_t smem_u32(const void* p) {
    uint32_t a;
    asm("{ .reg .u64 t; cvta.to.shared.u64 t, %1; cvt.u32.u64 %0, t; }"
        : "=r"(a) : "l"(p));
    return a;
}
__device__ __forceinline__ void ldmx4(uint32_t& r0, uint32_t& r1, uint32_t& r2,
                                      uint32_t& r3, uint32_t addr) {
    asm volatile("ldmatrix.sync.aligned.m8n8.x4.shared.b16 {%0,%1,%2,%3}, [%4];"
                 : "=r"(r0), "=r"(r1), "=r"(r2), "=r"(r3) : "r"(addr));
}
__device__ __forceinline__ void mma16816(float* c, uint32_t a0, uint32_t a1,
                                         uint32_t a2, uint32_t a3,
                                         uint32_t b0, uint32_t b1) {
    asm volatile(
        "mma.sync.aligned.m16n8k16.row.col.f32.f16.f16.f32 "
        "{%0,%1,%2,%3}, {%4,%5,%6,%7}, {%8,%9}, {%0,%1,%2,%3};"
        : "+f"(c[0]), "+f"(c[1]), "+f"(c[2]), "+f"(c[3])
        : "r"(a0), "r"(a1), "r"(a2), "r"(a3), "r"(b0), "r"(b1));
}
__device__ __forceinline__ float fast_ex2(float x) {
    float r;
    asm("ex2.approx.ftz.f32 %0, %1;" : "=f"(r) : "f"(x));
    return r;
}
__device__ __forceinline__ void cpa16(uint32_t sdst, const void* gsrc) {
    asm volatile("cp.async.cg.shared.global [%0], [%1], 16;"
                 :: "r"(sdst), "l"(gsrc) : "memory");
}
__device__ __forceinline__ void cpa_commit() {
    asm volatile("cp.async.commit_group;" ::: "memory");
}
__device__ __forceinline__ void cpa_wait0() {
    asm volatile("cp.async.wait_group 0;" ::: "memory");
}

__device__ __forceinline__ void stage_tile(uint32_t sdst, const uint4* gsrc, int tid) {
    #pragma unroll
    for (int it = 0; it < 8; it++) {
        int idx = it * 256 + tid;
        int r = idx >> 4, c = idx & 15;
        cpa16(sdst + r * ROWB + c * 16, gsrc + idx);
    }
}

// replay-safe grid barrier: counter only grows; target = next multiple of GRID
__device__ __forceinline__ void grid_barrier(int tid) {
    __syncthreads();
    if (tid == 0) {
        __threadfence();
        unsigned arrival = atomicAdd(&g_bar, 1u) + 1u;
        unsigned target = ((arrival + GRID - 1u) / GRID) * GRID;
        while (*(volatile unsigned*)&g_bar < target) {}
        __threadfence();
    }
    __syncthreads();
}

// ---------------- single fused persistent kernel ----------------------------
__global__ __launch_bounds__(256, 2) void fused_kernel(
    const float* __restrict__ in, float* __restrict__ out) {
    extern __shared__ char smem[];
    const int tid  = threadIdx.x;
    const int lane = tid & 31;
    const int wid  = tid >> 5;
    const int wrow = wid >> 2;
    const int wcol = wid & 3;
    const uint32_t sb = smem_u32(smem);
    float* sred = (float*)(smem + SMEM_RED);

    // ====== phase 1: normalize -> pre-scaled fp16, MLP=4, zero accs =========
    {
        const int gw = blockIdx.x * 8 + wid;           // 0..2367
        if (gw < 2048) {                               // 2048 warps x 4 rows
            const int r0 = gw * 4;
            float4 v[4];
            #pragma unroll
            for (int r = 0; r < 4; r++)                // 4 loads in flight
                v[r] = ((const float4*)(in + (size_t)(r0 + r) * D))[lane];
            float ss[4];
            #pragma unroll
            for (int r = 0; r < 4; r++)
                ss[r] = v[r].x * v[r].x + v[r].y * v[r].y +
                        v[r].z * v[r].z + v[r].w * v[r].w;
            #pragma unroll
            for (int o = 16; o; o >>= 1)
                #pragma unroll
                for (int r = 0; r < 4; r++)
                    ss[r] += __shfl_xor_sync(0xffffffffu, ss[r], o);
            #pragma unroll
            for (int r = 0; r < 4; r++) {
                float sc = rsqrtf(ss[r]) * PRE_SCALE;
                union { __half2 h[2]; uint2 u; } pk;
                pk.h[0] = __floats2half2_rn(v[r].x * sc, v[r].y * sc);
                pk.h[1] = __floats2half2_rn(v[r].z * sc, v[r].w * sc);
                ((uint2*)g_hv)[(r0 + r) * 32 + lane] = pk.u;
            }
            if (lane < 4) { g_total[r0 + lane] = 0.f; g_pos[r0 + lane] = 0.f; }
        }
        if (blockIdx.x == 0 && tid == 0) g_loss = 0.f;
    }
    grid_barrier(tid);

    // ====== phase 2: persistent HMMA Gram ====================================
    int t  = (int)((long long)blockIdx.x * NTILES / GRID);
    int t1 = (int)((long long)(blockIdx.x + 1) * NTILES / GRID);
    int br = 0, base = 0;
    while (t >= base + (NT - br)) { base += NT - br; br++; }
    int bc = br + (t - base);

    uint32_t aAddr[4];
    #pragma unroll
    for (int i = 0; i < 4; i++)
        aAddr[i] = sb + SMEM_A +
                   (wrow * 64 + i * 16 + (lane & 15)) * ROWB + (lane >> 4) * 16;
    const uint32_t bLane = (wcol * 32 + (lane & 7) + ((lane >> 4) & 1) * 8) * ROWB +
                           ((lane >> 3) & 1) * 16;

    while (t < t1) {
        stage_tile(sb + SMEM_A, (const uint4*)(G_H + (size_t)br * 128 * D), tid);
        stage_tile(sb + SMEM_B0, (const uint4*)(G_H + (size_t)bc * 128 * D), tid);
        cpa_commit(); cpa_wait0();
        __syncthreads();

        float rs_acc[8];
        #pragma unroll
        for (int q = 0; q < 8; q++) rs_acc[q] = 0.f;
        int buf = 0;

        for (;;) {
            const bool diag = (bc == br);
            const bool next_same = (t + 1 < t1) && (bc + 1 < NT);
            if (next_same) {
                stage_tile(sb + (buf ? SMEM_B0 : SMEM_B1),
                           (const uint4*)(G_H + (size_t)(bc + 1) * 128 * D), tid);
                cpa_commit();
            }

            const uint32_t bbase = sb + (buf ? SMEM_B1 : SMEM_B0) + bLane;
            float acc[4][4][4];
            #pragma unroll
            for (int i = 0; i < 4; i++)
                #pragma unroll
                for (int j = 0; j < 4; j++)
                    #pragma unroll
                    for (int r = 0; r < 4; r++) acc[i][j][r] = 0.f;

            uint32_t bf[2][8];
            ldmx4(bf[0][0], bf[0][1], bf[0][2], bf[0][3], bbase);
            ldmx4(bf[0][4], bf[0][5], bf[0][6], bf[0][7], bbase + 16 * ROWB);
            #pragma unroll
            for (int ks = 0; ks < 8; ks++) {
                const int cur = ks & 1, nxt = cur ^ 1;
                if (ks < 7) {
                    ldmx4(bf[nxt][0], bf[nxt][1], bf[nxt][2], bf[nxt][3],
                          bbase + (ks + 1) * 32);
                    ldmx4(bf[nxt][4], bf[nxt][5], bf[nxt][6], bf[nxt][7],
                          bbase + 16 * ROWB + (ks + 1) * 32);
                }
                #pragma unroll
                for (int i = 0; i < 4; i++) {
                    uint32_t a0, a1, a2, a3;
                    ldmx4(a0, a1, a2, a3, aAddr[i] + ks * 32);
                    #pragma unroll
                    for (int j = 0; j < 4; j++)
                        mma16816(acc[i][j], a0, a1, a2, a3,
                                 bf[cur][j * 2], bf[cur][j * 2 + 1]);
                }
            }

            const unsigned m = 0xffffffffu;
            if (diag) {
                float rt[8];
                #pragma unroll
                for (int q = 0; q < 8; q++) rt[q] = 0.f;
                #pragma unroll
                for (int i = 0; i < 4; i++)
                    #pragma unroll
                    for (int j = 0; j < 4; j++) {
                        rt[i*2]   += fast_ex2(acc[i][j][0]) + fast_ex2(acc[i][j][1]);
                        rt[i*2+1] += fast_ex2(acc[i][j][2]) + fast_ex2(acc[i][j][3]);
                    }
                #pragma unroll
                for (int q = 0; q < 8; q++) {
                    rt[q] += __shfl_xor_sync(m, rt[q], 1);
                    rt[q] += __shfl_xor_sync(m, rt[q], 2);
                    if ((lane & 3) == 0) rs_acc[q] += rt[q];   // flush re-reduces
                }
                if ((lane & 3) == 0) {
                    #pragma unroll
                    for (int i = 0; i < 4; i++)
                        #pragma unroll
                        for (int h = 0; h < 2; h++)
                            sred[wcol*128 + wrow*64 + i*16 + (lane>>2) + h*8] = rt[i*2+h];
                }
                cpa_wait0();
                __syncthreads();
                if (tid < 128) {
                    int h = tid >> 6;
                    g_pos[br * 128 + tid] =
                        sred[(2*h)*128 + tid] + sred[(2*h+1)*128 + tid];
                }
                __syncthreads();
            } else {
                float cs[8];
                #pragma unroll
                for (int q = 0; q < 8; q++) cs[q] = 0.f;
                #pragma unroll
                for (int i = 0; i < 4; i++)
                    #pragma unroll
                    for (int j = 0; j < 4; j++) {
                        float e0 = fast_ex2(acc[i][j][0]);
                        float e1 = fast_ex2(acc[i][j][1]);
                        float e2 = fast_ex2(acc[i][j][2]);
                        float e3 = fast_ex2(acc[i][j][3]);
                        rs_acc[i*2]   += e0 + e1;
                        rs_acc[i*2+1] += e2 + e3;
                        cs[j*2]   += e0 + e2;
                        cs[j*2+1] += e1 + e3;
                    }
                #pragma unroll
                for (int q = 0; q < 8; q++) {
                    cs[q] += __shfl_xor_sync(m, cs[q], 4);
                    cs[q] += __shfl_xor_sync(m, cs[q], 8);
                    cs[q] += __shfl_xor_sync(m, cs[q], 16);
                }
                if (lane < 4) {
                    const int colbase = bc * 128 + wcol * 32 + lane * 2;
                    #pragma unroll
                    for (int j = 0; j < 4; j++) {
                        atomicAdd(&g_total[colbase + j * 8],     cs[j*2]);
                        atomicAdd(&g_total[colbase + j * 8 + 1], cs[j*2+1]);
                    }
                }
                cpa_wait0();
                __syncthreads();
            }

            t++; bc++;
            if (!next_same) break;
            buf ^= 1;
        }

        // flush accumulated row sums for band br
        __syncthreads();
        const unsigned m = 0xffffffffu;
        float rf[8];
        #pragma unroll
        for (int q = 0; q < 8; q++) {
            float v = rs_acc[q];
            v += __shfl_xor_sync(m, v, 1);
            v += __shfl_xor_sync(m, v, 2);
            rf[q] = v;
        }
        if ((lane & 3) == 0) {
            #pragma unroll
            for (int i = 0; i < 4; i++)
                #pragma unroll
                for (int h = 0; h < 2; h++)
                    sred[wcol*128 + wrow*64 + i*16 + (lane>>2) + h*8] = rf[i*2+h];
        }
        __syncthreads();
        if (tid < 128)
            atomicAdd(&g_total[br * 128 + tid],
                      sred[tid] + sred[128+tid] + sred[256+tid] + sred[384+tid]);
        __syncthreads();

        if (t < t1 && bc >= NT) { br++; bc = br; }
    }

    // ====== phase 3: loss ====================================================
    grid_barrier(tid);                             // all g_total/g_pos complete
    {
        const int gtid = blockIdx.x * 256 + tid;
        float s = 0.f;
        if (gtid < N)
            s = __logf(g_total[gtid]) - __logf(g_pos[gtid]);
        #pragma unroll
        for (int o = 16; o; o >>= 1) s += __shfl_xor_sync(0xffffffffu, s, o);
        __shared__ float wsum[8];
        if (lane == 0) wsum[wid] = s;
        __syncthreads();
        if (tid == 0 && blockIdx.x * 256 < N) {
            float bs = 0.f;
            #pragma unroll
            for (int i = 0; i < 8; i++) bs += wsum[i];
            atomicAdd(&g_loss, bs);
        }
    }
    grid_barrier(tid);
    if (blockIdx.x == 0 && tid == 0)
        out[0] = g_loss / (float)N;
}

// ---------------- launch ----------------------------------------------------
extern "C" void kernel_launch(void* const* d_in, const int* in_sizes, int n_in,
                              void* d_out, int out_size) {
    const float* feature = (const float*)d_in[0];
    cudaFuncSetAttribute(fused_kernel,
                         cudaFuncAttributeMaxDynamicSharedMemorySize, SMEM_BYTES);
    fused_kernel<<<GRID, 256, SMEM_BYTES>>>(feature, (float*)d_out);
}

// round 13
// speedup vs baseline: 1.0548x; 1.0548x over previous
#include <cuda_runtime.h>
#include <cuda_fp16.h>
#include <cstdint>
#include <math.h>

constexpr int N = 8192;
constexpr int D = 128;
// features pre-scaled by sqrt(10*log2(e)); Gram accumulators are exp2 args
constexpr float PRE_SCALE = 3.79828256f;

constexpr int NT     = 64;
constexpr int NTILES = 2080;
constexpr int GRID   = 296;                  // 2 CTAs x 148 SMs, all resident

constexpr int TILEB  = 32768;                // 128 rows x 256B, contiguous
constexpr int SMEM_A   = 0;
constexpr int SMEM_B0  = 32768;
constexpr int SMEM_B1  = 65536;
constexpr int SMEM_RED = 98304;              // 2048 B reduction scratch
constexpr int SMEM_BAR = 100352;             // 3 mbarriers
constexpr int SMEM_BYTES = 100352 + 64;

// g_hv layout: row r occupies bytes [r*256, r*256+256); 16B chunk c stored at
// physical chunk c ^ (r & 7)  (XOR on low 3 bits; bit 3 = 128B half untouched)
__device__ uint4 g_hv[N * D / 8];
__device__ float g_total[N];
__device__ float g_pos[N];
__device__ float g_loss;
__device__ unsigned g_bar;
#define G_HB ((char*)g_hv)

__device__ __forceinline__ uint32_t smem_u32(const void* p) {
    uint32_t a;
    asm("{ .reg .u64 t; cvta.to.shared.u64 t, %1; cvt.u32.u64 %0, t; }"
        : "=r"(a) : "l"(p));
    return a;
}
__device__ __forceinline__ void ldmx4(uint32_t& r0, uint32_t& r1, uint32_t& r2,
                                      uint32_t& r3, uint32_t addr) {
    asm volatile("ldmatrix.sync.aligned.m8n8.x4.shared.b16 {%0,%1,%2,%3}, [%4];"
                 : "=r"(r0), "=r"(r1), "=r"(r2), "=r"(r3) : "r"(addr));
}
__device__ __forceinline__ void mma16816(float* c, uint32_t a0, uint32_t a1,
                                         uint32_t a2, uint32_t a3,
                                         uint32_t b0, uint32_t b1) {
    asm volatile(
        "mma.sync.aligned.m16n8k16.row.col.f32.f16.f16.f32 "
        "{%0,%1,%2,%3}, {%4,%5,%6,%7}, {%8,%9}, {%0,%1,%2,%3};"
        : "+f"(c[0]), "+f"(c[1]), "+f"(c[2]), "+f"(c[3])
        : "r"(a0), "r"(a1), "r"(a2), "r"(a3), "r"(b0), "r"(b1));
}
__device__ __forceinline__ float fast_ex2(float x) {
    float r;
    asm("ex2.approx.ftz.f32 %0, %1;" : "=f"(r) : "f"(x));
    return r;
}
__device__ __forceinline__ void mbar_init(uint32_t a, uint32_t cnt) {
    asm volatile("mbarrier.init.shared.b64 [%0], %1;" :: "r"(a), "r"(cnt) : "memory");
}
__device__ __forceinline__ void mbar_expect(uint32_t a, uint32_t bytes) {
    asm volatile("mbarrier.arrive.expect_tx.shared.b64 _, [%0], %1;"
                 :: "r"(a), "r"(bytes) : "memory");
}
__device__ __forceinline__ void mbar_wait(uint32_t a, uint32_t parity) {
    asm volatile(
        "{\n\t.reg .pred P;\n\t"
        "WL%=:\n\t"
        "mbarrier.try_wait.parity.acquire.cta.shared::cta.b64 P, [%0], %1, 0x989680;\n\t"
        "@P bra WD%=;\n\t"
        "bra WL%=;\n\t"
        "WD%=:\n\t}"
        :: "r"(a), "r"(parity) : "memory");
}
// one-shot contiguous bulk copy: 32KB tile, gmem -> smem, completes on mbar
__device__ __forceinline__ void bulk_stage(uint32_t dst, const void* src,
                                           uint32_t mbar) {
    mbar_expect(mbar, TILEB);
    asm volatile(
        "cp.async.bulk.shared::cta.global.mbarrier::complete_tx::bytes "
        "[%0], [%1], %2, [%3];"
        :: "r"(dst), "l"(src), "r"(TILEB), "r"(mbar) : "memory");
}

// replay-safe grid barrier
__device__ __forceinline__ void grid_barrier(int tid) {
    __syncthreads();
    if (tid == 0) {
        __threadfence();
        unsigned arrival = atomicAdd(&g_bar, 1u) + 1u;
        unsigned target = ((arrival + GRID - 1u) / GRID) * GRID;
        while (*(volatile unsigned*)&g_bar < target) {}
        __threadfence();
    }
    __syncthreads();
}

// ---------------- single fused persistent kernel ----------------------------
__global__ __launch_bounds__(256, 2) void fused_kernel(
    const float* __restrict__ in, float* __restrict__ out) {
    extern __shared__ char smem[];
    const int tid  = threadIdx.x;
    const int lane = tid & 31;
    const int wid  = tid >> 5;
    const int wrow = wid >> 2;
    const int wcol = wid & 3;
    const uint32_t sb = smem_u32(smem);
    float* sred = (float*)(smem + SMEM_RED);
    const uint32_t mbA  = sb + SMEM_BAR;
    const uint32_t mbB0 = sb + SMEM_BAR + 8;
    const uint32_t mbB1 = sb + SMEM_BAR + 16;

    if (tid == 0) { mbar_init(mbA, 1); mbar_init(mbB0, 1); mbar_init(mbB1, 1); }

    // ====== phase 1: normalize -> pre-scaled fp16, swizzled layout ==========
    {
        const int gw = blockIdx.x * 8 + wid;
        if (gw < 2048) {
            const int r0 = gw * 4;
            float4 v[4];
            #pragma unroll
            for (int r = 0; r < 4; r++)
                v[r] = ((const float4*)(in + (size_t)(r0 + r) * D))[lane];
            float ss[4];
            #pragma unroll
            for (int r = 0; r < 4; r++)
                ss[r] = v[r].x * v[r].x + v[r].y * v[r].y +
                        v[r].z * v[r].z + v[r].w * v[r].w;
            #pragma unroll
            for (int o = 16; o; o >>= 1)
                #pragma unroll
                for (int r = 0; r < 4; r++)
                    ss[r] += __shfl_xor_sync(0xffffffffu, ss[r], o);
            #pragma unroll
            for (int r = 0; r < 4; r++) {
                float sc = rsqrtf(ss[r]) * PRE_SCALE;
                union { __half2 h[2]; uint2 u; } pk;
                pk.h[0] = __floats2half2_rn(v[r].x * sc, v[r].y * sc);
                pk.h[1] = __floats2half2_rn(v[r].z * sc, v[r].w * sc);
                const int row = r0 + r;
                // lane owns 8 bytes: logical chunk = lane>>1, half = lane&1
                const uint32_t swz = ((((lane >> 1) ^ (row & 7)) << 4) |
                                      ((lane & 1) << 3));
                *(uint2*)(G_HB + (size_t)row * 256 + swz) = pk.u;
            }
            if (lane < 4) { g_total[r0 + lane] = 0.f; g_pos[r0 + lane] = 0.f; }
        }
        if (blockIdx.x == 0 && tid == 0) g_loss = 0.f;
    }
    grid_barrier(tid);

    // ====== phase 2: persistent HMMA Gram (bulk-copy staged) =================
    int t  = (int)((long long)blockIdx.x * NTILES / GRID);
    int t1 = (int)((long long)(blockIdx.x + 1) * NTILES / GRID);
    int br = 0, base = 0;
    while (t >= base + (NT - br)) { base += NT - br; br++; }
    int bc = br + (t - base);

    // swizzled ldmatrix addressing, 256B linear rows:
    // physical chunk = logical chunk ^ (row&7); logical chunk = (ks<<1)|hi
    // split: bit4 = hi ^ (lane&1);  bits5-7 = (ks<<5) ^ ((lane&6)<<4)
    const uint32_t cbA = ((((lane >> 4) ^ lane) & 1) << 4);
    const uint32_t cbB = ((((lane >> 3) ^ lane) & 1) << 4);
    const uint32_t kx  = (lane & 6) << 4;
    uint32_t aAddr[4];
    #pragma unroll
    for (int i = 0; i < 4; i++)
        aAddr[i] = sb + SMEM_A + (wrow * 64 + i * 16 + (lane & 15)) * 256 + cbA;
    const uint32_t bRowOff =
        (wcol * 32 + (lane & 7) + ((lane >> 4) & 1) * 8) * 256 + cbB;

    int phA = 0, phB[2] = {0, 0};

    while (t < t1) {
        if (tid == 0) {
            bulk_stage(sb + SMEM_A,  G_HB + (size_t)br * TILEB, mbA);
            bulk_stage(sb + SMEM_B0, G_HB + (size_t)bc * TILEB, mbB0);
        }
        mbar_wait(mbA, phA); phA ^= 1;

        float rs_acc[8];
        #pragma unroll
        for (int q = 0; q < 8; q++) rs_acc[q] = 0.f;
        int buf = 0;

        for (;;) {
            const bool diag = (bc == br);
            const bool next_same = (t + 1 < t1) && (bc + 1 < NT);
            if (tid == 0 && next_same)
                bulk_stage(sb + (buf ? SMEM_B0 : SMEM_B1),
                           G_HB + (size_t)(bc + 1) * TILEB, buf ? mbB0 : mbB1);

            mbar_wait(buf ? mbB1 : mbB0, phB[buf]); phB[buf] ^= 1;

            const uint32_t bbase = sb + (buf ? SMEM_B1 : SMEM_B0) + bRowOff;
            float acc[4][4][4];
            #pragma unroll
            for (int i = 0; i < 4; i++)
                #pragma unroll
                for (int j = 0; j < 4; j++)
                    #pragma unroll
                    for (int r = 0; r < 4; r++) acc[i][j][r] = 0.f;

            uint32_t bf[2][8];
            {
                const uint32_t k0 = 0 ^ kx;
                ldmx4(bf[0][0], bf[0][1], bf[0][2], bf[0][3], bbase + k0);
                ldmx4(bf[0][4], bf[0][5], bf[0][6], bf[0][7], bbase + k0 + 4096);
            }
            #pragma unroll
            for (int ks = 0; ks < 8; ks++) {
                const int cur = ks & 1, nxt = cur ^ 1;
                const uint32_t koff = ((uint32_t)(ks << 5)) ^ kx;
                if (ks < 7) {
                    const uint32_t kn = ((uint32_t)((ks + 1) << 5)) ^ kx;
                    ldmx4(bf[nxt][0], bf[nxt][1], bf[nxt][2], bf[nxt][3],
                          bbase + kn);
                    ldmx4(bf[nxt][4], bf[nxt][5], bf[nxt][6], bf[nxt][7],
                          bbase + kn + 4096);
                }
                #pragma unroll
                for (int i = 0; i < 4; i++) {
                    uint32_t a0, a1, a2, a3;
                    ldmx4(a0, a1, a2, a3, aAddr[i] + koff);
                    #pragma unroll
                    for (int j = 0; j < 4; j++)
                        mma16816(acc[i][j], a0, a1, a2, a3,
                                 bf[cur][j * 2], bf[cur][j * 2 + 1]);
                }
            }

            const unsigned m = 0xffffffffu;
            if (diag) {
                float rt[8];
                #pragma unroll
                for (int q = 0; q < 8; q++) rt[q] = 0.f;
                #pragma unroll
                for (int i = 0; i < 4; i++)
                    #pragma unroll
                    for (int j = 0; j < 4; j++) {
                        rt[i*2]   += fast_ex2(acc[i][j][0]) + fast_ex2(acc[i][j][1]);
                        rt[i*2+1] += fast_ex2(acc[i][j][2]) + fast_ex2(acc[i][j][3]);
                    }
                #pragma unroll
                for (int q = 0; q < 8; q++) {
                    rt[q] += __shfl_xor_sync(m, rt[q], 1);
                    rt[q] += __shfl_xor_sync(m, rt[q], 2);
                    if ((lane & 3) == 0) rs_acc[q] += rt[q];   // flush re-reduces
                }
                if ((lane & 3) == 0) {
                    #pragma unroll
                    for (int i = 0; i < 4; i++)
                        #pragma unroll
                        for (int h = 0; h < 2; h++)
                            sred[wcol*128 + wrow*64 + i*16 + (lane>>2) + h*8] = rt[i*2+h];
                }
                __syncthreads();
                if (tid < 128) {
                    int h = tid >> 6;
                    g_pos[br * 128 + tid] =
                        sred[(2*h)*128 + tid] + sred[(2*h+1)*128 + tid];
                }
                __syncthreads();
            } else {
                float cs[8];
                #pragma unroll
                for (int q = 0; q < 8; q++) cs[q] = 0.f;
                #pragma unroll
                for (int i = 0; i < 4; i++)
                    #pragma unroll
                    for (int j = 0; j < 4; j++) {
                        float e0 = fast_ex2(acc[i][j][0]);
                        float e1 = fast_ex2(acc[i][j][1]);
                        float e2 = fast_ex2(acc[i][j][2]);
                        float e3 = fast_ex2(acc[i][j][3]);
                        rs_acc[i*2]   += e0 + e1;
                        rs_acc[i*2+1] += e2 + e3;
                        cs[j*2]   += e0 + e2;
                        cs[j*2+1] += e1 + e3;
                    }
                #pragma unroll
                for (int q = 0; q < 8; q++) {
                    cs[q] += __shfl_xor_sync(m, cs[q], 4);
                    cs[q] += __shfl_xor_sync(m, cs[q], 8);
                    cs[q] += __shfl_xor_sync(m, cs[q], 16);
                }
                if (lane < 4) {
                    const int colbase = bc * 128 + wcol * 32 + lane * 2;
                    #pragma unroll
                    for (int j = 0; j < 4; j++) {
                        atomicAdd(&g_total[colbase + j * 8],     cs[j*2]);
                        atomicAdd(&g_total[colbase + j * 8 + 1], cs[j*2+1]);
                    }
                }
                __syncthreads();       // all done reading buf -> restage safe
            }

            t++; bc++;
            if (!next_same) break;
            buf ^= 1;
        }

        // flush accumulated row sums for band br
        __syncthreads();
        const unsigned m = 0xffffffffu;
        float rf[8];
        #pragma unroll
        for (int q = 0; q < 8; q++) {
            float v = rs_acc[q];
            v += __shfl_xor_sync(m, v, 1);
            v += __shfl_xor_sync(m, v, 2);
            rf[q] = v;
        }
        if ((lane & 3) == 0) {
            #pragma unroll
            for (int i = 0; i < 4; i++)
                #pragma unroll
                for (int h = 0; h < 2; h++)
                    sred[wcol*128 + wrow*64 + i*16 + (lane>>2) + h*8] = rf[i*2+h];
        }
        __syncthreads();
        if (tid < 128)
            atomicAdd(&g_total[br * 128 + tid],
                      sred[tid] + sred[128+tid] + sred[256+tid] + sred[384+tid]);
        __syncthreads();

        if (t < t1 && bc >= NT) { br++; bc = br; }
    }

    // ====== phase 3: loss ====================================================
    grid_barrier(tid);
    {
        const int gtid = blockIdx.x * 256 + tid;
        float s = 0.f;
        if (gtid < N)
            s = __logf(g_total[gtid]) - __logf(g_pos[gtid]);
        #pragma unroll
        for (int o = 16; o; o >>= 1) s += __shfl_xor_sync(0xffffffffu, s, o);
        __shared__ float wsum[8];
        if (lane == 0) wsum[wid] = s;
        __syncthreads();
        if (tid == 0 && blockIdx.x * 256 < N) {
            float bs = 0.f;
            #pragma unroll
            for (int i = 0; i < 8; i++) bs += wsum[i];
            atomicAdd(&g_loss, bs);
        }
    }
    grid_barrier(tid);
    if (blockIdx.x == 0 && tid == 0)
        out[0] = g_loss / (float)N;
}

// ---------------- launch ----------------------------------------------------
extern "C" void kernel_launch(void* const* d_in, const int* in_sizes, int n_in,
                              void* d_out, int out_size) {
    const float* feature = (const float*)d_in[0];
    cudaFuncSetAttribute(fused_kernel,
                         cudaFuncAttributeMaxDynamicSharedMemorySize, SMEM_BYTES);
    fused_kernel<<<GRID, 256, SMEM_BYTES>>>(feature, (float*)d_out);
}